// round 12
// baseline (speedup 1.0000x reference)
#include <cuda_runtime.h>
#include <cuda_bf16.h>

#define MAX_NODES 524288   // >= 500,000, static scratch (no allocation allowed)

// Statically zero-initialized; every launch leaves these back at zero
// (scratch reset by combine_kernel, loss acc by its thread 0),
// so CUDA-graph replays are deterministic.
__device__ float4 g_scratch[MAX_NODES];   // per-node accumulated half-adjustments
__device__ float4 g_pospad[MAX_NODES];    // pos padded to float4 for 1-LDG gathers
__device__ double g_loss_acc;

// ---------------------------------------------------------------------------
// 1) Pad pos [N,3] -> float4 [N], smem-staged for fully coalesced traffic.
// ---------------------------------------------------------------------------
__global__ void __launch_bounds__(256) pad_pos_kernel(const float* __restrict__ pos,
                                                      int N, int n_pos) {
    __shared__ float s[768];
    int t = threadIdx.x;
    int node_base = blockIdx.x * 256;
    int float_base = node_base * 3;          // multiple of 768 -> 16B aligned

    if (float_base + 768 <= n_pos) {
        if (t < 192) {
            float4 v = reinterpret_cast<const float4*>(pos)[float_base / 4 + t];
            s[4 * t + 0] = v.x; s[4 * t + 1] = v.y;
            s[4 * t + 2] = v.z; s[4 * t + 3] = v.w;
        }
    } else {
        for (int k = t; k < 768; k += 256) {
            int idx = float_base + k;
            s[k] = (idx < n_pos) ? pos[idx] : 0.0f;
        }
    }
    __syncthreads();

    int i = node_base + t;
    if (i < N)
        g_pospad[i] = make_float4(s[3 * t], s[3 * t + 1], s[3 * t + 2], 0.0f);
}

// ---------------------------------------------------------------------------
// 2) Edge kernel: 4 edges per thread, int4 index loads, float4 gathers,
//    red.global.add.v4.f32 scatters, shared-mem target table (broadcast LDS).
// ---------------------------------------------------------------------------
__device__ __forceinline__ void red_add_v4(float4* addr, float a, float b, float c) {
    asm volatile("red.global.add.v4.f32 [%0], {%1, %2, %3, %4};"
                 :: "l"(addr), "f"(a), "f"(b), "f"(c), "f"(0.0f)
                 : "memory");
}

__device__ __forceinline__ float process_edge(int r, int c, int b,
                                              const float* __restrict__ s_tgt) {
    float4 pr = g_pospad[r];
    float4 pc = g_pospad[c];
    float dx = pr.x - pc.x;
    float dy = pr.y - pc.y;
    float dz = pr.z - pc.z;
    float d2 = fmaxf(dx * dx + dy * dy + dz * dz, 1e-12f);
    float rsq = rsqrtf(d2);
    float len = d2 * rsq;                 // = sqrt(d2) >= 1e-6

    float tgt = s_tgt[b];                 // b in [0,4] by construction

    float ratio = fminf(fmaxf(tgt * rsq, 0.8f), 1.2f);
    // half-adjustment = bv*(ratio-1)*CORRECTION_FACTOR*0.5 = bv*(ratio-1)*0.05
    float s = (ratio - 1.0f) * 0.05f;
    float ax = dx * s, ay = dy * s, az = dz * s;

    red_add_v4(&g_scratch[r],  ax,  ay,  az);
    red_add_v4(&g_scratch[c], -ax, -ay, -az);

    return fabsf(len - tgt);
}

__global__ void __launch_bounds__(256) edge_kernel(const int* __restrict__ rows,
                            const int* __restrict__ cols,
                            const int* __restrict__ bond_types,
                            const float* __restrict__ target_lengths,
                            const float* __restrict__ length_adjustment,
                            int E) {
    __shared__ float s_tgt[5];
    if (threadIdx.x < 5)
        s_tgt[threadIdx.x] = target_lengths[threadIdx.x] + length_adjustment[threadIdx.x];
    __syncthreads();

    int t = blockIdx.x * blockDim.x + threadIdx.x;
    int base = t * 4;
    float err = 0.0f;

    if (base + 3 < E) {
        int4 r4 = *reinterpret_cast<const int4*>(rows + base);
        int4 c4 = *reinterpret_cast<const int4*>(cols + base);
        int4 b4 = *reinterpret_cast<const int4*>(bond_types + base);
        err += process_edge(r4.x, c4.x, b4.x, s_tgt);
        err += process_edge(r4.y, c4.y, b4.y, s_tgt);
        err += process_edge(r4.z, c4.z, b4.z, s_tgt);
        err += process_edge(r4.w, c4.w, b4.w, s_tgt);
    } else {
        for (int e = base; e < E; e++)
            err += process_edge(rows[e], cols[e], bond_types[e], s_tgt);
    }

    // Block reduction of the length-error partial sums.
    #pragma unroll
    for (int o = 16; o > 0; o >>= 1)
        err += __shfl_down_sync(0xffffffff, err, o);

    __shared__ float warpsum[8];
    int lane = threadIdx.x & 31;
    int wid  = threadIdx.x >> 5;
    if (lane == 0) warpsum[wid] = err;
    __syncthreads();
    if (wid == 0) {
        int nwarps = blockDim.x >> 5;
        float v = (lane < nwarps) ? warpsum[lane] : 0.0f;
        #pragma unroll
        for (int o = 4; o > 0; o >>= 1)
            v += __shfl_down_sync(0xffffffff, v, o);
        if (lane == 0)
            atomicAdd(&g_loss_acc, (double)v);
    }
}

// ---------------------------------------------------------------------------
// 3) Combine: out = pospad + scratch (both coalesced float4 reads), reset
//    scratch, smem-staged float4 output stores. Block 0 thread 0 writes loss.
// ---------------------------------------------------------------------------
__global__ void __launch_bounds__(256) combine_kernel(float* __restrict__ out,
                                                      int N, int n_pos,
                                                      int loss_idx, float scale) {
    __shared__ float s[768];
    int t = threadIdx.x;
    int node_base = blockIdx.x * 256;
    int i = node_base + t;

    if (i < N) {
        float4 p = g_pospad[i];
        float4 a = g_scratch[i];
        g_scratch[i] = make_float4(0.0f, 0.0f, 0.0f, 0.0f);
        s[3 * t + 0] = p.x + a.x;
        s[3 * t + 1] = p.y + a.y;
        s[3 * t + 2] = p.z + a.z;
    }
    __syncthreads();

    int float_base = node_base * 3;
    if (float_base + 768 <= n_pos) {
        if (t < 192) {
            float4 v = make_float4(s[4 * t], s[4 * t + 1], s[4 * t + 2], s[4 * t + 3]);
            reinterpret_cast<float4*>(out)[float_base / 4 + t] = v;
        }
    } else {
        for (int k = t; k < 768; k += 256) {
            int idx = float_base + k;
            if (idx < n_pos) out[idx] = s[k];
        }
    }

    if (blockIdx.x == 0 && t == 0) {
        out[loss_idx] = (float)g_loss_acc * scale;
        g_loss_acc = 0.0;
    }
}

// ---------------------------------------------------------------------------
extern "C" void kernel_launch(void* const* d_in, const int* in_sizes, int n_in,
                              void* d_out, int out_size) {
    const float* pos = (const float*)d_in[0];   // [N,3] f32
    const int*   ei  = (const int*)d_in[1];     // [2,E] int32
    const int*   bt  = (const int*)d_in[2];     // [E]   int32
    const float* tl  = (const float*)d_in[3];   // [5]
    const float* la  = (const float*)d_in[4];   // [5]
    float*       out = (float*)d_out;

    const int n_pos = in_sizes[0];              // 3*N
    const int N     = n_pos / 3;
    const int E     = in_sizes[2];
    const int* rows = ei;
    const int* cols = ei + E;

    const int threads = 256;
    const int nblocks_n = (N + threads - 1) / threads;

    pad_pos_kernel<<<nblocks_n, threads>>>(pos, N, n_pos);

    const int nthreads_e = (E + 3) / 4;
    edge_kernel<<<(nthreads_e + threads - 1) / threads, threads>>>(
        rows, cols, bt, tl, la, E);

    combine_kernel<<<nblocks_n, threads>>>(out, N, n_pos, /*loss_idx=*/n_pos,
                                           0.1f / (float)E);
}

// round 15
// speedup vs baseline: 1.0005x; 1.0005x over previous
#include <cuda_runtime.h>
#include <cuda_bf16.h>

#define MAX_NODES 524288   // >= 500,000, static scratch (no allocation allowed)

// Statically zero-initialized; every launch leaves these back at zero
// (scratch reset by combine_kernel, loss acc by its thread 0),
// so CUDA-graph replays are deterministic.
__device__ float4 g_scratch[MAX_NODES];   // per-node accumulated half-adjustments
__device__ float4 g_pospad[MAX_NODES];    // pos padded to float4 for 1-LDG gathers
__device__ double g_loss_acc;

// ---------------------------------------------------------------------------
// 1) Pad pos [N,3] -> float4 [N], smem-staged for fully coalesced traffic.
// ---------------------------------------------------------------------------
__global__ void __launch_bounds__(256) pad_pos_kernel(const float* __restrict__ pos,
                                                      int N, int n_pos) {
    __shared__ float s[768];
    int t = threadIdx.x;
    int node_base = blockIdx.x * 256;
    int float_base = node_base * 3;          // multiple of 768 -> 16B aligned

    if (float_base + 768 <= n_pos) {
        if (t < 192) {
            float4 v = reinterpret_cast<const float4*>(pos)[float_base / 4 + t];
            s[4 * t + 0] = v.x; s[4 * t + 1] = v.y;
            s[4 * t + 2] = v.z; s[4 * t + 3] = v.w;
        }
    } else {
        for (int k = t; k < 768; k += 256) {
            int idx = float_base + k;
            s[k] = (idx < n_pos) ? pos[idx] : 0.0f;
        }
    }
    __syncthreads();

    int i = node_base + t;
    if (i < N)
        g_pospad[i] = make_float4(s[3 * t], s[3 * t + 1], s[3 * t + 2], 0.0f);
}

// ---------------------------------------------------------------------------
// 2) Edge kernel: 4 edges per thread, int4 index loads, float4 gathers,
//    red.global.add.v4.f32 scatters, shared-mem target table (broadcast LDS).
// ---------------------------------------------------------------------------
__device__ __forceinline__ void red_add_v4(float4* addr, float a, float b, float c) {
    asm volatile("red.global.add.v4.f32 [%0], {%1, %2, %3, %4};"
                 :: "l"(addr), "f"(a), "f"(b), "f"(c), "f"(0.0f)
                 : "memory");
}

__device__ __forceinline__ float process_edge(int r, int c, int b,
                                              const float* __restrict__ s_tgt) {
    float4 pr = g_pospad[r];
    float4 pc = g_pospad[c];
    float dx = pr.x - pc.x;
    float dy = pr.y - pc.y;
    float dz = pr.z - pc.z;
    float d2 = fmaxf(dx * dx + dy * dy + dz * dz, 1e-12f);
    float rsq = rsqrtf(d2);
    float len = d2 * rsq;                 // = sqrt(d2) >= 1e-6

    float tgt = s_tgt[b];                 // b in [0,4] by construction

    float ratio = fminf(fmaxf(tgt * rsq, 0.8f), 1.2f);
    // half-adjustment = bv*(ratio-1)*CORRECTION_FACTOR*0.5 = bv*(ratio-1)*0.05
    float s = (ratio - 1.0f) * 0.05f;
    float ax = dx * s, ay = dy * s, az = dz * s;

    red_add_v4(&g_scratch[r],  ax,  ay,  az);
    red_add_v4(&g_scratch[c], -ax, -ay, -az);

    return fabsf(len - tgt);
}

__global__ void __launch_bounds__(256) edge_kernel(const int* __restrict__ rows,
                            const int* __restrict__ cols,
                            const int* __restrict__ bond_types,
                            const float* __restrict__ target_lengths,
                            const float* __restrict__ length_adjustment,
                            int E) {
    __shared__ float s_tgt[5];
    if (threadIdx.x < 5)
        s_tgt[threadIdx.x] = target_lengths[threadIdx.x] + length_adjustment[threadIdx.x];
    __syncthreads();

    int t = blockIdx.x * blockDim.x + threadIdx.x;
    int base = t * 4;
    float err = 0.0f;

    if (base + 3 < E) {
        int4 r4 = *reinterpret_cast<const int4*>(rows + base);
        int4 c4 = *reinterpret_cast<const int4*>(cols + base);
        int4 b4 = *reinterpret_cast<const int4*>(bond_types + base);
        err += process_edge(r4.x, c4.x, b4.x, s_tgt);
        err += process_edge(r4.y, c4.y, b4.y, s_tgt);
        err += process_edge(r4.z, c4.z, b4.z, s_tgt);
        err += process_edge(r4.w, c4.w, b4.w, s_tgt);
    } else {
        for (int e = base; e < E; e++)
            err += process_edge(rows[e], cols[e], bond_types[e], s_tgt);
    }

    // Block reduction of the length-error partial sums.
    #pragma unroll
    for (int o = 16; o > 0; o >>= 1)
        err += __shfl_down_sync(0xffffffff, err, o);

    __shared__ float warpsum[8];
    int lane = threadIdx.x & 31;
    int wid  = threadIdx.x >> 5;
    if (lane == 0) warpsum[wid] = err;
    __syncthreads();
    if (wid == 0) {
        int nwarps = blockDim.x >> 5;
        float v = (lane < nwarps) ? warpsum[lane] : 0.0f;
        #pragma unroll
        for (int o = 4; o > 0; o >>= 1)
            v += __shfl_down_sync(0xffffffff, v, o);
        if (lane == 0)
            atomicAdd(&g_loss_acc, (double)v);
    }
}

// ---------------------------------------------------------------------------
// 3) Combine: out = pospad + scratch (both coalesced float4 reads), reset
//    scratch, smem-staged float4 output stores. Block 0 thread 0 writes loss.
// ---------------------------------------------------------------------------
__global__ void __launch_bounds__(256) combine_kernel(float* __restrict__ out,
                                                      int N, int n_pos,
                                                      int loss_idx, float scale) {
    __shared__ float s[768];
    int t = threadIdx.x;
    int node_base = blockIdx.x * 256;
    int i = node_base + t;

    if (i < N) {
        float4 p = g_pospad[i];
        float4 a = g_scratch[i];
        g_scratch[i] = make_float4(0.0f, 0.0f, 0.0f, 0.0f);
        s[3 * t + 0] = p.x + a.x;
        s[3 * t + 1] = p.y + a.y;
        s[3 * t + 2] = p.z + a.z;
    }
    __syncthreads();

    int float_base = node_base * 3;
    if (float_base + 768 <= n_pos) {
        if (t < 192) {
            float4 v = make_float4(s[4 * t], s[4 * t + 1], s[4 * t + 2], s[4 * t + 3]);
            reinterpret_cast<float4*>(out)[float_base / 4 + t] = v;
        }
    } else {
        for (int k = t; k < 768; k += 256) {
            int idx = float_base + k;
            if (idx < n_pos) out[idx] = s[k];
        }
    }

    if (blockIdx.x == 0 && t == 0) {
        out[loss_idx] = (float)g_loss_acc * scale;
        g_loss_acc = 0.0;
    }
}

// ---------------------------------------------------------------------------
extern "C" void kernel_launch(void* const* d_in, const int* in_sizes, int n_in,
                              void* d_out, int out_size) {
    const float* pos = (const float*)d_in[0];   // [N,3] f32
    const int*   ei  = (const int*)d_in[1];     // [2,E] int32
    const int*   bt  = (const int*)d_in[2];     // [E]   int32
    const float* tl  = (const float*)d_in[3];   // [5]
    const float* la  = (const float*)d_in[4];   // [5]
    float*       out = (float*)d_out;

    const int n_pos = in_sizes[0];              // 3*N
    const int N     = n_pos / 3;
    const int E     = in_sizes[2];
    const int* rows = ei;
    const int* cols = ei + E;

    const int threads = 256;
    const int nblocks_n = (N + threads - 1) / threads;

    pad_pos_kernel<<<nblocks_n, threads>>>(pos, N, n_pos);

    const int nthreads_e = (E + 3) / 4;
    edge_kernel<<<(nthreads_e + threads - 1) / threads, threads>>>(
        rows, cols, bt, tl, la, E);

    combine_kernel<<<nblocks_n, threads>>>(out, N, n_pos, /*loss_idx=*/n_pos,
                                           0.1f / (float)E);
}

// round 16
// speedup vs baseline: 1.0021x; 1.0016x over previous
#include <cuda_runtime.h>
#include <cuda_bf16.h>

#define MAX_NODES 524288   // >= 500,000, static scratch (no allocation allowed)

// Statically zero-initialized; every launch leaves these back at zero
// (scratch reset by combine_kernel, loss acc by its thread 0),
// so CUDA-graph replays are deterministic.
__device__ float4 g_scratch[MAX_NODES];   // per-node accumulated half-adjustments
__device__ float4 g_pospad[MAX_NODES];    // pos padded to float4 for 1-LDG gathers
__device__ double g_loss_acc;

// ---------------------------------------------------------------------------
// 1) Pad pos [N,3] -> float4 [N], smem-staged for fully coalesced traffic.
// ---------------------------------------------------------------------------
__global__ void __launch_bounds__(256) pad_pos_kernel(const float* __restrict__ pos,
                                                      int N, int n_pos) {
    __shared__ float s[768];
    int t = threadIdx.x;
    int node_base = blockIdx.x * 256;
    int float_base = node_base * 3;          // multiple of 768 -> 16B aligned

    if (float_base + 768 <= n_pos) {
        if (t < 192) {
            float4 v = reinterpret_cast<const float4*>(pos)[float_base / 4 + t];
            s[4 * t + 0] = v.x; s[4 * t + 1] = v.y;
            s[4 * t + 2] = v.z; s[4 * t + 3] = v.w;
        }
    } else {
        for (int k = t; k < 768; k += 256) {
            int idx = float_base + k;
            s[k] = (idx < n_pos) ? pos[idx] : 0.0f;
        }
    }
    __syncthreads();

    int i = node_base + t;
    if (i < N)
        g_pospad[i] = make_float4(s[3 * t], s[3 * t + 1], s[3 * t + 2], 0.0f);
}

// ---------------------------------------------------------------------------
// 2) Edge kernel: 4 edges per thread, int4 index loads, float4 gathers,
//    red.global.add.v4.f32 scatters, shared-mem target table (broadcast LDS).
// ---------------------------------------------------------------------------
__device__ __forceinline__ void red_add_v4(float4* addr, float a, float b, float c) {
    asm volatile("red.global.add.v4.f32 [%0], {%1, %2, %3, %4};"
                 :: "l"(addr), "f"(a), "f"(b), "f"(c), "f"(0.0f)
                 : "memory");
}

__device__ __forceinline__ float process_edge(int r, int c, int b,
                                              const float* __restrict__ s_tgt) {
    float4 pr = g_pospad[r];
    float4 pc = g_pospad[c];
    float dx = pr.x - pc.x;
    float dy = pr.y - pc.y;
    float dz = pr.z - pc.z;
    float d2 = fmaxf(dx * dx + dy * dy + dz * dz, 1e-12f);
    float rsq = rsqrtf(d2);
    float len = d2 * rsq;                 // = sqrt(d2) >= 1e-6

    float tgt = s_tgt[b];                 // b in [0,4] by construction

    float ratio = fminf(fmaxf(tgt * rsq, 0.8f), 1.2f);
    // half-adjustment = bv*(ratio-1)*CORRECTION_FACTOR*0.5 = bv*(ratio-1)*0.05
    float s = (ratio - 1.0f) * 0.05f;
    float ax = dx * s, ay = dy * s, az = dz * s;

    red_add_v4(&g_scratch[r],  ax,  ay,  az);
    red_add_v4(&g_scratch[c], -ax, -ay, -az);

    return fabsf(len - tgt);
}

__global__ void __launch_bounds__(256) edge_kernel(const int* __restrict__ rows,
                            const int* __restrict__ cols,
                            const int* __restrict__ bond_types,
                            const float* __restrict__ target_lengths,
                            const float* __restrict__ length_adjustment,
                            int E) {
    __shared__ float s_tgt[5];
    if (threadIdx.x < 5)
        s_tgt[threadIdx.x] = target_lengths[threadIdx.x] + length_adjustment[threadIdx.x];
    __syncthreads();

    int t = blockIdx.x * blockDim.x + threadIdx.x;
    int base = t * 4;
    float err = 0.0f;

    if (base + 3 < E) {
        int4 r4 = *reinterpret_cast<const int4*>(rows + base);
        int4 c4 = *reinterpret_cast<const int4*>(cols + base);
        int4 b4 = *reinterpret_cast<const int4*>(bond_types + base);
        err += process_edge(r4.x, c4.x, b4.x, s_tgt);
        err += process_edge(r4.y, c4.y, b4.y, s_tgt);
        err += process_edge(r4.z, c4.z, b4.z, s_tgt);
        err += process_edge(r4.w, c4.w, b4.w, s_tgt);
    } else {
        for (int e = base; e < E; e++)
            err += process_edge(rows[e], cols[e], bond_types[e], s_tgt);
    }

    // Block reduction of the length-error partial sums.
    #pragma unroll
    for (int o = 16; o > 0; o >>= 1)
        err += __shfl_down_sync(0xffffffff, err, o);

    __shared__ float warpsum[8];
    int lane = threadIdx.x & 31;
    int wid  = threadIdx.x >> 5;
    if (lane == 0) warpsum[wid] = err;
    __syncthreads();
    if (wid == 0) {
        int nwarps = blockDim.x >> 5;
        float v = (lane < nwarps) ? warpsum[lane] : 0.0f;
        #pragma unroll
        for (int o = 4; o > 0; o >>= 1)
            v += __shfl_down_sync(0xffffffff, v, o);
        if (lane == 0)
            atomicAdd(&g_loss_acc, (double)v);
    }
}

// ---------------------------------------------------------------------------
// 3) Combine: out = pospad + scratch (both coalesced float4 reads), reset
//    scratch, smem-staged float4 output stores. Block 0 thread 0 writes loss.
// ---------------------------------------------------------------------------
__global__ void __launch_bounds__(256) combine_kernel(float* __restrict__ out,
                                                      int N, int n_pos,
                                                      int loss_idx, float scale) {
    __shared__ float s[768];
    int t = threadIdx.x;
    int node_base = blockIdx.x * 256;
    int i = node_base + t;

    if (i < N) {
        float4 p = g_pospad[i];
        float4 a = g_scratch[i];
        g_scratch[i] = make_float4(0.0f, 0.0f, 0.0f, 0.0f);
        s[3 * t + 0] = p.x + a.x;
        s[3 * t + 1] = p.y + a.y;
        s[3 * t + 2] = p.z + a.z;
    }
    __syncthreads();

    int float_base = node_base * 3;
    if (float_base + 768 <= n_pos) {
        if (t < 192) {
            float4 v = make_float4(s[4 * t], s[4 * t + 1], s[4 * t + 2], s[4 * t + 3]);
            reinterpret_cast<float4*>(out)[float_base / 4 + t] = v;
        }
    } else {
        for (int k = t; k < 768; k += 256) {
            int idx = float_base + k;
            if (idx < n_pos) out[idx] = s[k];
        }
    }

    if (blockIdx.x == 0 && t == 0) {
        out[loss_idx] = (float)g_loss_acc * scale;
        g_loss_acc = 0.0;
    }
}

// ---------------------------------------------------------------------------
extern "C" void kernel_launch(void* const* d_in, const int* in_sizes, int n_in,
                              void* d_out, int out_size) {
    const float* pos = (const float*)d_in[0];   // [N,3] f32
    const int*   ei  = (const int*)d_in[1];     // [2,E] int32
    const int*   bt  = (const int*)d_in[2];     // [E]   int32
    const float* tl  = (const float*)d_in[3];   // [5]
    const float* la  = (const float*)d_in[4];   // [5]
    float*       out = (float*)d_out;

    const int n_pos = in_sizes[0];              // 3*N
    const int N     = n_pos / 3;
    const int E     = in_sizes[2];
    const int* rows = ei;
    const int* cols = ei + E;

    const int threads = 256;
    const int nblocks_n = (N + threads - 1) / threads;

    pad_pos_kernel<<<nblocks_n, threads>>>(pos, N, n_pos);

    const int nthreads_e = (E + 3) / 4;
    edge_kernel<<<(nthreads_e + threads - 1) / threads, threads>>>(
        rows, cols, bt, tl, la, E);

    combine_kernel<<<nblocks_n, threads>>>(out, N, n_pos, /*loss_idx=*/n_pos,
                                           0.1f / (float)E);
}